// round 10
// baseline (speedup 1.0000x reference)
#include <cuda_runtime.h>
#include <cuda_bf16.h>

// FINAL — converged champion (rounds 4 & 8: 4.61/4.67us bench, 4.32/4.42us ncu).
//
// Fully collapsed closed form (exact algebra, validated rounds 1-8):
//   P = |A0|^2 + |A1|^2 + 2*gamma*Re(A0*conj(A1))
//   A0 = d1*(d0*v0[0]v1[0] - e0*v0[1]v1[1])
//   A1 = e1*(e0*v0[1]v1[0] - d0*v0[0]v1[1])
//   v_w = RZ(Wz_w)RY(pi*tanh(q_w)+Wy_w)|0>,  gamma = sin(th2+Wy2)*cos(Wz2)
// key register, W_k, W_int, q3 and all wire-3 weights: provably irrelevant
// (disjoint registers -> product state; CRY controlled on query; CRZ diagonal;
// unitarity of the conditioned key evolution marginalizes to 1).
// Kernel is at the launch/ramp overhead floor: issue 5.6%, fma 0.3%, one wave.

__global__ void __launch_bounds__(128, 1)
vqa_kernel(const float4* __restrict__ query4,
           const float* __restrict__ Wqy,   // (2,4)
           const float* __restrict__ Wqz,   // (2,4)
           float* __restrict__ out) {
    int b = blockIdx.x * blockDim.x + threadIdx.x;

    const float PI = 3.14159265358979323846f;
    float4 qv = __ldg(&query4[(long long)b * 16]);   // floats 0..3 of 64-float row

    // th_i = pi * tanh(q_i), i = 0..2
    float qin[3] = {qv.x, qv.y, qv.z};
    float th[3];
#pragma unroll
    for (int i = 0; i < 3; i++) {
        float e = __expf(2.0f * qin[i]);
        th[i] = (1.0f - __fdividef(2.0f, e + 1.0f)) * PI;
    }

    float C0, S0, C1, S1, d0, e0, d1, e1;
    __sincosf(0.5f * (th[0] + Wqy[0]), &S0, &C0);
    __sincosf(0.5f * (th[1] + Wqy[1]), &S1, &C1);
    __sincosf(0.5f * (th[0] + Wqy[4]), &e0, &d0);
    __sincosf(0.5f * (th[1] + Wqy[5]), &e1, &d1);

    float sz0, cz0, sz1, cz1;
    __sincosf(0.5f * Wqz[0], &sz0, &cz0);
    __sincosf(0.5f * Wqz[1], &sz1, &cz1);

    float gamma = __sinf(th[2] + Wqy[2]) * __cosf(Wqz[2]);

    // v0[0]=C0 e^{-i p0}, v0[1]=S0 e^{+i p0}; wire 1 likewise
    float v00r = C0 * cz0, v00i = -C0 * sz0;
    float v01r = S0 * cz0, v01i =  S0 * sz0;
    float v10r = C1 * cz1, v10i = -C1 * sz1;
    float v11r = S1 * cz1, v11i =  S1 * sz1;

    float t00r = v00r * v10r - v00i * v10i, t00i = v00r * v10i + v00i * v10r;
    float t11r = v01r * v11r - v01i * v11i, t11i = v01r * v11i + v01i * v11r;
    float t10r = v01r * v10r - v01i * v10i, t10i = v01r * v10i + v01i * v10r;
    float t01r = v00r * v11r - v00i * v11i, t01i = v00r * v11i + v00i * v11r;

    float A0r = d1 * (d0 * t00r - e0 * t11r);
    float A0i = d1 * (d0 * t00i - e0 * t11i);
    float A1r = e1 * (e0 * t10r - d0 * t01r);
    float A1i = e1 * (e0 * t10i - d0 * t01i);

    out[b] = A0r * A0r + A0i * A0i + A1r * A1r + A1i * A1i
           + 2.0f * gamma * (A0r * A1r + A0i * A1i);
}

extern "C" void kernel_launch(void* const* d_in, const int* in_sizes, int n_in,
                              void* d_out, int out_size) {
    const float4* query = (const float4*)d_in[0];
    const float* W_q_y = (const float*)d_in[2];
    const float* W_q_z = (const float*)d_in[3];
    float* out = (float*)d_out;
    int B = out_size;                 // 8192

    const int threads = 128;          // measured optimum: 64 blocks x 128 threads
    const int blocks = B / threads;
    vqa_kernel<<<blocks, threads>>>(query, W_q_y, W_q_z, out);
}

// round 11
// speedup vs baseline: 1.5035x; 1.5035x over previous
#include <cuda_runtime.h>
#include <cuda_bf16.h>

// FINAL — converged champion (byte-identical across rounds 4/8/10:
// bench {4.61, 4.67, 6.88}us, ncu {4.32, 4.42, 4.64}us, rel_err 9.4e-7 fixed).
//
// Fully collapsed closed form (exact algebra, validated rounds 1-10):
//   P = |A0|^2 + |A1|^2 + 2*gamma*Re(A0*conj(A1))
//   A0 = d1*(d0*v0[0]v1[0] - e0*v0[1]v1[1])
//   A1 = e1*(e0*v0[1]v1[0] - d0*v0[0]v1[1])
//   v_w = RZ(Wz_w)RY(pi*tanh(q_w)+Wy_w)|0>,  gamma = sin(th2+Wy2)*cos(Wz2)
// key register, W_k, W_int, q3 and all wire-3 weights: provably irrelevant
// (disjoint registers -> product state; CRY controlled on query; CRZ diagonal;
// unitarity of the conditioned key evolution marginalizes to 1).
// Kernel sits at the launch/DVFS-ramp floor (issue ~5%, fma ~0.4%, one wave);
// remaining bench variance is harness timer noise, not kernel behavior.

__global__ void __launch_bounds__(128, 1)
vqa_kernel(const float4* __restrict__ query4,
           const float* __restrict__ Wqy,   // (2,4)
           const float* __restrict__ Wqz,   // (2,4)
           float* __restrict__ out) {
    int b = blockIdx.x * blockDim.x + threadIdx.x;

    const float PI = 3.14159265358979323846f;
    float4 qv = __ldg(&query4[(long long)b * 16]);   // floats 0..3 of 64-float row

    // th_i = pi * tanh(q_i), i = 0..2
    float qin[3] = {qv.x, qv.y, qv.z};
    float th[3];
#pragma unroll
    for (int i = 0; i < 3; i++) {
        float e = __expf(2.0f * qin[i]);
        th[i] = (1.0f - __fdividef(2.0f, e + 1.0f)) * PI;
    }

    float C0, S0, C1, S1, d0, e0, d1, e1;
    __sincosf(0.5f * (th[0] + Wqy[0]), &S0, &C0);
    __sincosf(0.5f * (th[1] + Wqy[1]), &S1, &C1);
    __sincosf(0.5f * (th[0] + Wqy[4]), &e0, &d0);
    __sincosf(0.5f * (th[1] + Wqy[5]), &e1, &d1);

    float sz0, cz0, sz1, cz1;
    __sincosf(0.5f * Wqz[0], &sz0, &cz0);
    __sincosf(0.5f * Wqz[1], &sz1, &cz1);

    float gamma = __sinf(th[2] + Wqy[2]) * __cosf(Wqz[2]);

    // v0[0]=C0 e^{-i p0}, v0[1]=S0 e^{+i p0}; wire 1 likewise
    float v00r = C0 * cz0, v00i = -C0 * sz0;
    float v01r = S0 * cz0, v01i =  S0 * sz0;
    float v10r = C1 * cz1, v10i = -C1 * sz1;
    float v11r = S1 * cz1, v11i =  S1 * sz1;

    float t00r = v00r * v10r - v00i * v10i, t00i = v00r * v10i + v00i * v10r;
    float t11r = v01r * v11r - v01i * v11i, t11i = v01r * v11i + v01i * v11r;
    float t10r = v01r * v10r - v01i * v10i, t10i = v01r * v10i + v01i * v10r;
    float t01r = v00r * v11r - v00i * v11i, t01i = v00r * v11i + v00i * v11r;

    float A0r = d1 * (d0 * t00r - e0 * t11r);
    float A0i = d1 * (d0 * t00i - e0 * t11i);
    float A1r = e1 * (e0 * t10r - d0 * t01r);
    float A1i = e1 * (e0 * t10i - d0 * t01i);

    out[b] = A0r * A0r + A0i * A0i + A1r * A1r + A1i * A1i
           + 2.0f * gamma * (A0r * A1r + A0i * A1i);
}

extern "C" void kernel_launch(void* const* d_in, const int* in_sizes, int n_in,
                              void* d_out, int out_size) {
    const float4* query = (const float4*)d_in[0];
    const float* W_q_y = (const float*)d_in[2];
    const float* W_q_z = (const float*)d_in[3];
    float* out = (float*)d_out;
    int B = out_size;                 // 8192

    const int threads = 128;          // measured optimum: 64 blocks x 128 threads
    const int blocks = B / threads;
    vqa_kernel<<<blocks, threads>>>(query, W_q_y, W_q_z, out);
}